// round 16
// baseline (speedup 1.0000x reference)
#include <cuda_runtime.h>
#include <math.h>

#define NN4     (1024 * 1024 / 4)
#define TPB     256
#define NBLK    256              /* 256 blocks x 256 threads x 4 rows */
#define NCYC    4
#define DYNSM   (22 * 256 * 16)  /* sS(12 rows) + xb(10 rows) of float4 */

// ---------------- device scratch (allocations forbidden) --------------------
__device__ float4 g_S[16][NN4];    // Chebyshev basis s_0..s_14 (+slot 15 unused)
__device__ float  g_part[33][NBLK];
__device__ volatile unsigned g_gen;
__device__ unsigned g_arrive;

// ---------------- helpers ------------------------------------------------------
__device__ __forceinline__ float4 ns5(float4 C, float L, float R, float4 U, float4 D) {
    float4 n;
    n.x = L   + C.y + U.x + D.x;
    n.y = C.x + C.z + U.y + D.y;
    n.z = C.y + C.w + U.z + D.z;
    n.w = C.z + R   + U.w + D.w;
    return n;
}

__device__ __forceinline__ void latG(const float4* __restrict__ u4, float4 C,
                                     int li, int ri, int lane, float& L, float& R) {
    L = __shfl_up_sync(0xffffffffu, C.w, 1);
    R = __shfl_down_sync(0xffffffffu, C.x, 1);
    if (lane == 0)  L = ((const float*)u4)[li];
    if (lane == 31) R = ((const float*)u4)[ri];
}

__device__ __forceinline__ float dot4(float4 a, float4 b) {
    return a.x * b.x + a.y * b.y + a.z * b.z + a.w * b.w;
}

__device__ __forceinline__ float4 sub_half_ns(float4 NS, float4 P) { // -NS/2 - P
    float4 r;
    r.x = -0.5f * NS.x - P.x; r.y = -0.5f * NS.y - P.y;
    r.z = -0.5f * NS.z - P.z; r.w = -0.5f * NS.w - P.w;
    return r;
}

__device__ __forceinline__ float4 quarter_neg(float4 NS) {           // -NS/4
    float4 r;
    r.x = -0.25f * NS.x; r.y = -0.25f * NS.y;
    r.z = -0.25f * NS.z; r.w = -0.25f * NS.w;
    return r;
}

__device__ __forceinline__ float warpSum(float v) {
#pragma unroll
    for (int o = 16; o > 0; o >>= 1) v += __shfl_down_sync(0xffffffffu, v, o);
    return v;
}

// ---------------- the persistent kernel ------------------------------------------
__global__ void __launch_bounds__(TPB, 2) k_all(const float4* __restrict__ b,
                                                const float4* __restrict__ guess,
                                                float4* __restrict__ out) {
    int q = blockIdx.x, col = threadIdx.x;
    int lane = col & 31, warp = col >> 5, t = col;
    int r0 = q << 2;
    int cl = ((col << 2) - 1) & 1023, cr = ((col << 2) + 4) & 1023;
    int colL = (col + 255) & 255, colR = (col + 1) & 255;

    auto RO = [&](int d) { return (r0 + d) & 1023; };
    auto I4 = [&](int d) { return (RO(d) << 8) | col; };
    auto LI = [&](int d) { return (RO(d) << 10) | cl; };
    auto RI = [&](int d) { return (RO(d) << 10) | cr; };

    // dynamic shared: sS = 12 rows (s_i / L2), xb = 10 rows (s_{i-1} / L1 / L3)
    extern __shared__ float4 dyn[];
    float4 (*sS)[TPB] = (float4 (*)[TPB])dyn;
    float4 (*xb)[TPB] = (float4 (*)[TPB])(dyn + 12 * TPB);

    __shared__ float  sred[9][TPB / 32];
    __shared__ float  smu[33];
    __shared__ double mu[33];
    __shared__ double M[17][17];
    __shared__ double W[17][16];
    __shared__ double G[16][16], sf[16], rhs[16];
    __shared__ float  cs[16], ds[17];
    __shared__ unsigned sGen;

    // split barrier primitives (tid0 state in sGen)
    auto barArrive = [&]() {
        __syncthreads();
        if (t == 0) {
            __threadfence();
            unsigned g = g_gen;
            sGen = g;
            if (atomicAdd(&g_arrive, 1u) == (unsigned)(NBLK - 1)) {
                g_arrive = 0u;
                __threadfence();
                g_gen = g + 1u;
            }
        }
        __syncthreads();
    };
    auto barWait = [&]() {
        if (t == 0) {
            unsigned g = sGen;
            while (g_gen == g) { }
            __threadfence();
        }
        __syncthreads();
    };

    // x register-resident across the entire solve
    float4 x[4];
#pragma unroll
    for (int k = 0; k < 4; k++) x[k] = guess[I4(k)];

    // ---- cycle-0 residual: s_0 = b - A(guess) ----
    float4 s[4], p[4];
    {
        float4 XU = guess[I4(-1)], XD = guess[I4(4)];
        float Lx, Rx;
#pragma unroll
        for (int k = 0; k < 4; k++) {
            latG(guess, x[k], LI(k), RI(k), lane, Lx, Rx);
            float4 up = (k == 0) ? XU : x[k - 1];
            float4 dn = (k == 3) ? XD : x[k + 1];
            float4 NS = ns5(x[k], Lx, Rx, up, dn);
            float4 bb = b[I4(k)];
            float4 r;
            r.x = bb.x - (4.3f * x[k].x - NS.x);
            r.y = bb.y - (4.3f * x[k].y - NS.y);
            r.z = bb.z - (4.3f * x[k].z - NS.z);
            r.w = bb.w - (4.3f * x[k].w - NS.w);
            s[k] = r;
            g_S[0][I4(k)] = r;
        }
    }
    barArrive(); barWait();

    for (int c = 0; c < NCYC; c++) {
        // ---- 4 quad-steps: each computes s_{i+1..i+4} under ONE barrier ----
        for (int jj = 0; jj < 4; jj++) {
            int i = 4 * jj;
            const float4* __restrict__ Si = g_S[i];

            // populate sS (s_i rows d=-4..7) and xb (s_{i-1} rows d=-3..6)
#pragma unroll
            for (int k = 0; k < 4; k++) sS[k + 4][col] = s[k];
            sS[0][col]  = Si[I4(-4)]; sS[1][col]  = Si[I4(-3)];
            sS[2][col]  = Si[I4(-2)]; sS[3][col]  = Si[I4(-1)];
            sS[8][col]  = Si[I4(4)];  sS[9][col]  = Si[I4(5)];
            sS[10][col] = Si[I4(6)];  sS[11][col] = Si[I4(7)];
            if (i > 0) {
                const float4* __restrict__ Sm = g_S[i - 1];
#pragma unroll
                for (int k = 0; k < 4; k++) xb[k + 3][col] = p[k];
                xb[0][col] = Sm[I4(-3)]; xb[1][col] = Sm[I4(-2)];
                xb[2][col] = Sm[I4(-1)]; xb[7][col] = Sm[I4(4)];
                xb[8][col] = Sm[I4(5)];  xb[9][col] = Sm[I4(6)];
            }
            __syncthreads();

            // ---- level 1: rows d=-3..6 -> xb (in place over s_{i-1}) ----
            float aI = 0.f, bI = 0.f;
#pragma unroll
            for (int d = -3; d <= 6; d++) {
                float4 C = sS[d + 4][col];
                float  L = sS[d + 4][colL].w, R = sS[d + 4][colR].x;
                float4 NS = ns5(C, L, R, sS[d + 3][col], sS[d + 5][col]);
                float4 n = (i == 0) ? quarter_neg(NS) : sub_half_ns(NS, xb[d + 3][col]);
                if (d >= 0 && d <= 3) {
                    aI += dot4(C, C);
                    bI += dot4(C, n);
                    g_S[i + 1][I4(d)] = n;
                }
                xb[d + 3][col] = n;
            }
            __syncthreads();

            // ---- level 2: rows d=-2..5 -> sS (in place over s_i) ----
            float aI1 = 0.f, bI1 = 0.f;
#pragma unroll
            for (int d = -2; d <= 5; d++) {
                float4 C = xb[d + 3][col];
                float  L = xb[d + 3][colL].w, R = xb[d + 3][colR].x;
                float4 NS = ns5(C, L, R, xb[d + 2][col], xb[d + 4][col]);
                float4 n = sub_half_ns(NS, sS[d + 4][col]);
                if (d >= 0 && d <= 3) {
                    aI1 += dot4(C, C);
                    bI1 += dot4(C, n);
                    g_S[i + 2][I4(d)] = n;
                }
                sS[d + 4][col] = n;
            }
            __syncthreads();

            // ---- level 3: rows d=-1..4 -> xb (in place over L1) ----
            float aI2 = 0.f, bI2 = 0.f;
            float4 np[4];
#pragma unroll
            for (int d = -1; d <= 4; d++) {
                float4 C = sS[d + 4][col];
                float  L = sS[d + 4][colL].w, R = sS[d + 4][colR].x;
                float4 NS = ns5(C, L, R, sS[d + 3][col], sS[d + 5][col]);
                float4 n = sub_half_ns(NS, xb[d + 3][col]);
                if (d >= 0 && d <= 3) {
                    aI2 += dot4(C, C);
                    bI2 += dot4(C, n);
                    if (i < 12) g_S[i + 3][I4(d)] = n;   // s_15 kept in registers only
                    np[d] = n;
                }
                xb[d + 3][col] = n;
            }
            __syncthreads();

            // ---- level 4: rows d=0..3 -> registers ----
            float aI3 = 0.f, bI3 = 0.f, a16 = 0.f;
            float4 ns_[4];
#pragma unroll
            for (int d = 0; d <= 3; d++) {
                float4 C = xb[d + 3][col];
                float  L = xb[d + 3][colL].w, R = xb[d + 3][colR].x;
                float4 NS = ns5(C, L, R, xb[d + 2][col], xb[d + 4][col]);
                float4 n = sub_half_ns(NS, sS[d + 4][col]);
                aI3 += dot4(C, C);
                bI3 += dot4(C, n);
                if (jj == 3) a16 += dot4(n, n);
                else         g_S[i + 4][I4(d)] = n;
                ns_[d] = n;
            }

            // jj==3: partials must be visible at release -> write BEFORE arrive
            if (jj == 3) {
                float v;
                v = warpSum(aI);  if (lane == 0) sred[0][warp] = v;
                v = warpSum(bI);  if (lane == 0) sred[1][warp] = v;
                v = warpSum(aI1); if (lane == 0) sred[2][warp] = v;
                v = warpSum(bI1); if (lane == 0) sred[3][warp] = v;
                v = warpSum(aI2); if (lane == 0) sred[4][warp] = v;
                v = warpSum(bI2); if (lane == 0) sred[5][warp] = v;
                v = warpSum(aI3); if (lane == 0) sred[6][warp] = v;
                v = warpSum(bI3); if (lane == 0) sred[7][warp] = v;
                v = warpSum(a16); if (lane == 0) sred[8][warp] = v;
                __syncthreads();
                if (t < 9) {
                    float sum = 0.f;
#pragma unroll
                    for (int w = 0; w < TPB / 32; w++) sum += sred[t][w];
                    g_part[(t == 8) ? 32 : 24 + t][q] = sum;
                }
                barArrive();
            } else {
                barArrive();                 // stores visible; dots happen while waiting
                float v;
                v = warpSum(aI);  if (lane == 0) sred[0][warp] = v;
                v = warpSum(bI);  if (lane == 0) sred[1][warp] = v;
                v = warpSum(aI1); if (lane == 0) sred[2][warp] = v;
                v = warpSum(bI1); if (lane == 0) sred[3][warp] = v;
                v = warpSum(aI2); if (lane == 0) sred[4][warp] = v;
                v = warpSum(bI2); if (lane == 0) sred[5][warp] = v;
                v = warpSum(aI3); if (lane == 0) sred[6][warp] = v;
                v = warpSum(bI3); if (lane == 0) sred[7][warp] = v;
                __syncthreads();
                if (t < 8) {
                    float sum = 0.f;
#pragma unroll
                    for (int w = 0; w < TPB / 32; w++) sum += sred[t][w];
                    g_part[8 * jj + t][q] = sum;   // visible via NEXT barrier's fence
                }
            }
#pragma unroll
            for (int k = 0; k < 4; k++) { p[k] = np[k]; s[k] = ns_[k]; }
            barWait();
        }
        // registers now: p = s_15, s = s_16

        // ---- every block: reduce 33 moments + fp64 16x16 solve (redundant) ----
        for (int r = warp; r < 33; r += TPB / 32) {
            float sum = 0.f;
            for (int b2 = lane; b2 < NBLK; b2 += 32) sum += g_part[r][b2];
            sum = warpSum(sum);
            if (lane == 0) smu[r] = sum;
        }
        __syncthreads();
        if (t < 33) {
            double vv;
            if (t < 2) vv = (double)smu[t];
            else       vv = 2.0 * (double)smu[t] - (double)smu[t & 1];
            mu[t] = vv;
        }
        __syncthreads();
        for (int idx = t; idx < 289; idx += TPB) {
            int a = idx / 17, b2 = idx % 17;
            int d = a - b2; if (d < 0) d = -d;
            M[a][b2] = 0.5 * (mu[a + b2] + mu[d]);
        }
        __syncthreads();
        for (int idx = t; idx < 272; idx += TPB) {
            int r = idx / 16, b2 = idx % 16;
            double w = 4.3 * M[r][b2];
            w += (b2 == 0) ? 4.0 * M[r][1] : 2.0 * (M[r][b2 + 1] + M[r][b2 - 1]);
            W[r][b2] = w;
        }
        __syncthreads();
        {
            int a = t >> 4, b2 = t & 15;
            double g = 4.3 * W[a][b2];
            g += (a == 0) ? 4.0 * W[1][b2] : 2.0 * (W[a + 1][b2] + W[a - 1][b2]);
            G[a][b2] = g;
        }
        if (t < 16) {
            double r = 4.3 * M[t][0];
            r += (t == 0) ? 4.0 * M[1][0] : 2.0 * (M[t + 1][0] + M[t - 1][0]);
            rhs[t] = r;
        }
        __syncthreads();
        if (t == 0) {
            double tr = 0.0;
            for (int k = 0; k < 16; k++) tr += G[k][k];
            double ridge = 1e-12 + 1e-10 * (tr / 16.0);
            for (int k = 0; k < 16; k++) G[k][k] += ridge;
        }
        __syncthreads();
        for (int pp = 0; pp < 16; pp++) {
            if (t > pp && t < 16) sf[t] = G[t][pp] / G[pp][pp];
            __syncthreads();
            int r = t >> 4, cc = t & 15;
            if (r > pp && cc > pp) G[r][cc] -= sf[r] * G[pp][cc];
            if (t > pp && t < 16) rhs[t] -= sf[t] * rhs[pp];
            __syncthreads();
        }
        if (t == 0) {
            for (int pp = 15; pp >= 0; pp--) {
                double su = rhs[pp];
                for (int cc = pp + 1; cc < 16; cc++) su -= G[pp][cc] * rhs[cc];
                rhs[pp] = su / G[pp][pp];
            }
        }
        __syncthreads();
        if (t < 16) cs[t] = (float)rhs[t];
        if (t < 17) {
            double dv;
            if (t == 0)       dv = 4.3 * rhs[0] + 2.0 * rhs[1];
            else if (t == 1)  dv = 4.3 * rhs[1] + 4.0 * rhs[0] + 2.0 * rhs[2];
            else if (t <= 14) dv = 4.3 * rhs[t] + 2.0 * rhs[t - 1] + 2.0 * rhs[t + 1];
            else if (t == 15) dv = 4.3 * rhs[15] + 2.0 * rhs[14];
            else              dv = 2.0 * rhs[15];
            ds[t] = (float)dv;
        }
        __syncthreads();

        if (c == NCYC - 1) {
            // ---- final: x += sum c_k s_k, emit ----
#pragma unroll 2
            for (int kk = 0; kk < 15; kk++) {
                float y = cs[kk];
#pragma unroll
                for (int k = 0; k < 4; k++) {
                    float4 vv = g_S[kk][I4(k)];
                    x[k].x += y * vv.x; x[k].y += y * vv.y;
                    x[k].z += y * vv.z; x[k].w += y * vv.w;
                }
            }
            float y15 = cs[15];
#pragma unroll
            for (int k = 0; k < 4; k++) {
                x[k].x += y15 * p[k].x; x[k].y += y15 * p[k].y;
                x[k].z += y15 * p[k].z; x[k].w += y15 * p[k].w;
                out[I4(k)] = x[k];
            }
        } else {
            // ---- fused x update + analytic residual ----
            float4 racc[4];
#pragma unroll
            for (int k = 0; k < 4; k++) { racc[k].x = racc[k].y = racc[k].z = racc[k].w = 0.f; }
#pragma unroll 2
            for (int kk = 0; kk < 15; kk++) {
                float y = cs[kk];
                float e = (kk == 0) ? (1.0f - ds[0]) : -ds[kk];
#pragma unroll
                for (int k = 0; k < 4; k++) {
                    float4 vv = g_S[kk][I4(k)];
                    x[k].x += y * vv.x;    x[k].y += y * vv.y;
                    x[k].z += y * vv.z;    x[k].w += y * vv.w;
                    racc[k].x += e * vv.x; racc[k].y += e * vv.y;
                    racc[k].z += e * vv.z; racc[k].w += e * vv.w;
                }
            }
            float y15 = cs[15], d15 = ds[15], d16 = ds[16];
#pragma unroll
            for (int k = 0; k < 4; k++) {
                x[k].x += y15 * p[k].x;  x[k].y += y15 * p[k].y;
                x[k].z += y15 * p[k].z;  x[k].w += y15 * p[k].w;
                racc[k].x -= d15 * p[k].x + d16 * s[k].x;
                racc[k].y -= d15 * p[k].y + d16 * s[k].y;
                racc[k].z -= d15 * p[k].z + d16 * s[k].z;
                racc[k].w -= d15 * p[k].w + d16 * s[k].w;
                s[k] = racc[k];
                g_S[0][I4(k)] = racc[k];
            }
            barArrive(); barWait();
        }
    }
}

// ---------------- host orchestration ----------------------------------------
extern "C" void kernel_launch(void* const* d_in, const int* in_sizes, int n_in,
                              void* d_out, int out_size) {
    (void)in_sizes; (void)n_in; (void)out_size;
    const float4* src   = (const float4*)d_in[0];
    const float4* guess = (const float4*)d_in[1];
    float4* out = (float4*)d_out;

    cudaFuncSetAttribute(k_all, cudaFuncAttributeMaxDynamicSharedMemorySize, DYNSM);
    k_all<<<NBLK, TPB, DYNSM>>>(src, guess, out);
}